// round 7
// baseline (speedup 1.0000x reference)
#include <cuda_runtime.h>
#include <math.h>

#define SCALE1 0.17677669529663687f  // 32^-0.5

// ---------------- scratch (static device globals; no allocation) ------------
__device__ float g_proj1[16384*768];   // [q1 | q2 | kv2(k,v) | lepe_lin]
__device__ float g_xs_pre[4096*256];
__device__ float g_xs[4096*256];
__device__ float g_kv1[4096*256];
__device__ float g_cat[16384*256];     // [x1 | x2]
__device__ float g_pre[16384*256];     // cat + lepe
__device__ float g_part[4*512*1024];   // per-(h,qtile) partial key-prob sums
__device__ float g_gsum[4*1024];
__device__ float g_lm[4*4096];
__device__ float g_Wcat[256*768];
__device__ float g_bcat[768];
__device__ float g_srwT[1024*256];     // (seg*256+ic, oc)
__device__ float g_lwT[9*256];         // (tap, c)

// ---------------- helpers ---------------------------------------------------
__device__ __forceinline__ float wredmax(float v){
  #pragma unroll
  for(int o=16;o;o>>=1) v = fmaxf(v, __shfl_xor_sync(0xFFFFFFFFu, v, o));
  return v;
}
__device__ __forceinline__ float wredsum(float v){
  #pragma unroll
  for(int o=16;o;o>>=1) v += __shfl_xor_sync(0xFFFFFFFFu, v, o);
  return v;
}

// ---------------- weight prep ------------------------------------------------
__global__ void prep_k(const float* __restrict__ q1w, const float* __restrict__ q2w,
                       const float* __restrict__ kv2w, const float* __restrict__ lpw,
                       const float* __restrict__ q1b, const float* __restrict__ q2b,
                       const float* __restrict__ kv2b, const float* __restrict__ lpb,
                       const float* __restrict__ srw, const float* __restrict__ lcw)
{
  int i0 = blockIdx.x*blockDim.x + threadIdx.x;
  int st = gridDim.x*blockDim.x;
  for(int idx=i0; idx<256*768; idx+=st){
    int k = idx/768, c = idx%768;
    float v;
    if(c<128)      v = q1w[k*128+c];
    else if(c<256) v = q2w[k*128+c-128];
    else if(c<512) v = kv2w[k*256+c-256];
    else           v = lpw[k*256+c-512];
    g_Wcat[idx] = v;
  }
  for(int c=i0;c<768;c+=st)
    g_bcat[c] = (c<128)?q1b[c]:(c<256)?q2b[c-128]:(c<512)?kv2b[c-256]:lpb[c-512];
  for(int idx=i0; idx<1024*256; idx+=st){
    int k = idx>>8, oc = idx&255;
    int seg = k>>8, ic = k&255;
    g_srwT[idx] = srw[(oc*256+ic)*4 + seg];
  }
  for(int idx=i0; idx<9*256; idx+=st){
    int tap = idx>>8, c = idx&255;
    g_lwT[idx] = lcw[c*9+tap];
  }
}

// ---------------- tiled 64x64 GEMM, 256 thr, 4x4 micro ----------------------
// MODE 0: x(16384x256) @ Wcat(256x768)+bcat -> g_proj1
// MODE 1: gather-x(4096x1024) @ srwT(1024x256)+sr_b -> g_xs_pre
// MODE 2: g_xs(4096x256) @ kv1_w(256x256)+kv1_b -> g_kv1
// MODE 3: g_pre(16384x256) @ proj_w(256x256)+proj_b, x2 -> d_out
template<int MODE>
__global__ void gemm_k(const float* __restrict__ Aext, const float* __restrict__ Bext,
                       const float* __restrict__ bias, float* __restrict__ Cext)
{
  constexpr int K  = (MODE==1)?1024:256;
  constexpr int Nn = (MODE==0)?768:256;
  const float* A = (MODE==2)? g_xs : (MODE==3)? g_pre : Aext;
  const float* B = (MODE==0)? g_Wcat : (MODE==1)? g_srwT : Bext;
  const float* bi = (MODE==0)? g_bcat : bias;
  float* C = (MODE==0)? g_proj1 : (MODE==1)? g_xs_pre : (MODE==2)? g_kv1 : Cext;

  __shared__ float sA[16][68];
  __shared__ float sB[16][68];
  int t = threadIdx.x;
  int row0 = blockIdx.y*64, col0 = blockIdx.x*64;
  int la_m = t>>2, la_k = (t&3)<<2;
  int lb_k = t>>4, lb_n = (t&15)<<2;
  int tr = (t>>4)<<2, tc = (t&15)<<2;
  float acc[4][4] = {};
  for(int kt=0; kt<(K>>4); kt++){
    float4 a4;
    if(MODE==1){
      int r = row0+la_m;
      int b = r>>10, p = r&1023, i = p>>5, j = p&31;
      int k = (kt<<4)+la_k;
      int seg = k>>8, ic = k&255;
      int tok = ((2*i + (seg>>1))<<6) + 2*j + (seg&1);
      a4 = *(const float4*)(A + (size_t)((b<<12)+tok)*256 + ic);
    } else {
      a4 = *(const float4*)(A + (size_t)(row0+la_m)*K + (kt<<4)+la_k);
    }
    sA[la_k][la_m]=a4.x; sA[la_k+1][la_m]=a4.y;
    sA[la_k+2][la_m]=a4.z; sA[la_k+3][la_m]=a4.w;
    *(float4*)&sB[lb_k][lb_n] = *(const float4*)(B + (size_t)((kt<<4)+lb_k)*Nn + col0+lb_n);
    __syncthreads();
    #pragma unroll
    for(int kk=0;kk<16;kk++){
      float4 av=*(const float4*)&sA[kk][tr];
      float4 bv=*(const float4*)&sB[kk][tc];
      float ar[4]={av.x,av.y,av.z,av.w}, br[4]={bv.x,bv.y,bv.z,bv.w};
      #pragma unroll
      for(int i=0;i<4;i++)
        #pragma unroll
        for(int j=0;j<4;j++) acc[i][j] = fmaf(ar[i],br[j],acc[i][j]);
    }
    __syncthreads();
  }
  #pragma unroll
  for(int i=0;i<4;i++){
    int r = row0+tr+i;
    float4 v4;
    v4.x = acc[i][0]+bi[col0+tc+0];
    v4.y = acc[i][1]+bi[col0+tc+1];
    v4.z = acc[i][2]+bi[col0+tc+2];
    v4.w = acc[i][3]+bi[col0+tc+3];
    if(MODE==3){ v4.x*=2.f; v4.y*=2.f; v4.z*=2.f; v4.w*=2.f; }
    *(float4*)&C[(size_t)r*Nn + col0+tc] = v4;
  }
}

// ---------------- LayerNorm + exact GELU ------------------------------------
__global__ void ln_gelu_k(const float* __restrict__ nw, const float* __restrict__ nb){
  int r = blockIdx.x, c = threadIdx.x;
  float v = g_xs_pre[(size_t)r*256+c];
  float s = v, s2 = v*v;
  #pragma unroll
  for(int o=16;o;o>>=1){ s += __shfl_xor_sync(~0u,s,o); s2 += __shfl_xor_sync(~0u,s2,o); }
  __shared__ float rs[8], rs2[8];
  int w = c>>5, l = c&31;
  if(l==0){ rs[w]=s; rs2[w]=s2; }
  __syncthreads();
  if(w==0){
    float a=(l<8)?rs[l]:0.f, a2=(l<8)?rs2[l]:0.f;
    #pragma unroll
    for(int o=4;o;o>>=1){ a+=__shfl_xor_sync(~0u,a,o); a2+=__shfl_xor_sync(~0u,a2,o); }
    if(l==0){ rs[0]=a; rs2[0]=a2; }
  }
  __syncthreads();
  float m  = rs[0]*(1.f/256.f);
  float var= rs2[0]*(1.f/256.f) - m*m;
  float y  = (v-m)*rsqrtf(var+1e-5f)*nw[c] + nb[c];
  g_xs[(size_t)r*256+c] = 0.5f*y*(1.f+erff(y*0.70710678118f));
}

// ---------------- branch-1 attention (full score row in smem) ---------------
// grid (128 qtiles, 4 heads, 4 batch), 256 threads, dyn smem 153216 B
extern __shared__ float dsm[];
__global__ void attn1_k(){
  float* sS  = dsm;             // 32*1032
  float* sQ  = sS + 32*1032;    // 32*33
  float* sKV = sQ + 32*33;      // 128*33
  int t = threadIdx.x;
  int qt = blockIdx.x, h = blockIdx.y, b = blockIdx.z;
  int n0 = qt*32;
  for(int e=t;e<1024;e+=256){
    int q=e>>5, dd=e&31;
    sQ[q*33+dd] = g_proj1[((size_t)(b*4096+n0+q))*768 + h*32+dd];
  }
  // ---- scores: thread = (qb=t>>5 -> 4 queries, kb=t&31 -> keys kb+32u) ----
  int qb = t>>5, kb = t&31;
  for(int kt=0;kt<8;kt++){
    int m0 = kt*128;
    __syncthreads();
    for(int e=t;e<4096;e+=256){
      int mm=e>>5, dd=e&31;
      sKV[mm*33+dd] = g_kv1[((size_t)(b*1024+m0+mm))*256 + h*32+dd];
    }
    __syncthreads();
    float acc4[4][4] = {};
    #pragma unroll 8
    for(int dd=0;dd<32;dd++){
      float aq[4], ak[4];
      #pragma unroll
      for(int i=0;i<4;i++) aq[i] = sQ[(qb*4+i)*33+dd];
      #pragma unroll
      for(int u=0;u<4;u++) ak[u] = sKV[(kb+32*u)*33+dd];
      #pragma unroll
      for(int i=0;i<4;i++)
        #pragma unroll
        for(int u=0;u<4;u++) acc4[i][u] = fmaf(aq[i], ak[u], acc4[i][u]);
    }
    #pragma unroll
    for(int i=0;i<4;i++)
      #pragma unroll
      for(int u=0;u<4;u++)
        sS[(qb*4+i)*1032 + m0 + kb + 32*u] = acc4[i][u]*SCALE1;
  }
  __syncthreads();
  // ---- softmax: warp w handles queries w*4..w*4+3 ----
  int w = t>>5, l = t&31;
  for(int qi=0;qi<4;qi++){
    float* row = sS + (w*4+qi)*1032;
    float mx = -1e30f;
    #pragma unroll 8
    for(int i=0;i<32;i++) mx = fmaxf(mx, row[l+32*i]);
    mx = wredmax(mx);
    float sm = 0.f;
    #pragma unroll 8
    for(int i=0;i<32;i++){ float p=__expf(row[l+32*i]-mx); row[l+32*i]=p; sm+=p; }
    sm = wredsum(sm);
    float inv = 1.f/sm;
    #pragma unroll 8
    for(int i=0;i<32;i++) row[l+32*i] *= inv;
  }
  __syncthreads();
  // ---- per-key partial sums for g ----
  #pragma unroll
  for(int u=0;u<4;u++){
    int m = t + (u<<8);
    float s=0.f;
    #pragma unroll 8
    for(int q=0;q<32;q++) s += sS[q*1032+m];
    g_part[((size_t)(b*512 + h*128 + qt))*1024 + m] = s;
  }
  // ---- AV: key-split x4, thread tile 4q x 4dd ----
  int kq = t>>6, r2 = t&63;
  int qb2 = r2>>3, db = r2&7;
  float acc[4][4] = {};
  for(int kt=0;kt<8;kt++){
    int m0 = kt*128;
    __syncthreads();
    for(int e=t;e<4096;e+=256){
      int mm=e>>5, dd=e&31;
      sKV[mm*33+dd] = g_kv1[((size_t)(b*1024+m0+mm))*256 + 128 + h*32+dd];
    }
    __syncthreads();
    #pragma unroll 4
    for(int mm2=0;mm2<32;mm2++){
      int mm = kq*32+mm2;
      float p[4], vv[4];
      #pragma unroll
      for(int i=0;i<4;i++) p[i] = sS[(qb2*4+i)*1032 + m0+mm];
      #pragma unroll
      for(int u=0;u<4;u++) vv[u] = sKV[mm*33 + db*4+u];
      #pragma unroll
      for(int i=0;i<4;i++)
        #pragma unroll
        for(int u=0;u<4;u++) acc[i][u] = fmaf(p[i], vv[u], acc[i][u]);
    }
  }
  __syncthreads();   // done reading sS probs; reuse sS for partial reduction
  #pragma unroll
  for(int i=0;i<4;i++)
    #pragma unroll
    for(int u=0;u<4;u++)
      sS[kq*1024 + (qb2*4+i)*32 + db*4+u] = acc[i][u];
  __syncthreads();
  #pragma unroll
  for(int s2=0;s2<4;s2++){
    int oi = t + 256*s2;                 // 0..1023 = q*32+dd
    float v = sS[oi] + sS[1024+oi] + sS[2048+oi] + sS[3072+oi];
    int q = oi>>5, dd = oi&31;
    g_cat[((size_t)(b*4096+n0+q))*256 + h*32 + dd] = v;
  }
}

// ---------------- g reduction ------------------------------------------------
__global__ void gred_k(){
  int b = blockIdx.x, m = threadIdx.x;   // 1024 threads
  float s = 0.f;
  for(int p=0;p<512;p++) s += g_part[((size_t)(b*512+p))*1024 + m];
  g_gsum[b*1024+m] = s;
}

// ---------------- branch-2 window attention ----------------------------------
// grid (256 windows, 4 batch), 256 threads
__global__ void attn2_k(){
  __shared__ float sQ[4][16][33], sK[4][16][33], sV[4][16][33];
  __shared__ float sS[4][16][17];
  int t = threadIdx.x;
  int win = blockIdx.x, b = blockIdx.y;
  int i1 = win>>4, j1 = win&15;
  for(int e=t;e<2048;e+=256){
    int h=e>>9, rem=e&511, tk=rem>>5, dd=rem&31;
    int n = ((i1*4 + (tk>>2))<<6) + j1*4 + (tk&3);
    size_t base = ((size_t)(b*4096+n))*768 + h*32+dd;
    sQ[h][tk][dd] = g_proj1[base+128];
    sK[h][tk][dd] = g_proj1[base+256];
    sV[h][tk][dd] = g_proj1[base+384];
  }
  __syncthreads();
  int h = t>>6, q = (t>>2)&15, kg = t&3;
  #pragma unroll
  for(int k2=0;k2<4;k2++){
    int kk = kg*4+k2;
    float s = 0.f;
    #pragma unroll
    for(int dd=0;dd<32;dd++) s = fmaf(sQ[h][q][dd], sK[h][kk][dd], s);
    sS[h][q][kk] = s*SCALE1;
  }
  __syncthreads();
  if(kg==0){
    float* row = sS[h][q];
    float mx=-1e30f;
    #pragma unroll
    for(int kk=0;kk<16;kk++) mx = fmaxf(mx,row[kk]);
    float sm=0.f;
    #pragma unroll
    for(int kk=0;kk<16;kk++){ float p=__expf(row[kk]-mx); row[kk]=p; sm+=p; }
    float inv=1.f/sm;
    #pragma unroll
    for(int kk=0;kk<16;kk++) row[kk]*=inv;
  }
  __syncthreads();
  float acc[8]={};
  int dd0 = kg*8;
  #pragma unroll
  for(int kk=0;kk<16;kk++){
    float p = sS[h][q][kk];
    #pragma unroll
    for(int u=0;u<8;u++) acc[u] = fmaf(p, sV[h][kk][dd0+u], acc[u]);
  }
  {
    int n = ((i1*4+(q>>2))<<6) + j1*4 + (q&3);
    float* dst = &g_cat[((size_t)(b*4096+n))*256 + 128 + h*32 + dd0];
    #pragma unroll
    for(int u=0;u<8;u++) dst[u] = acc[u];
  }
  if(t<16){
    float s=0.f;
    #pragma unroll
    for(int h2=0;h2<4;h2++)
      #pragma unroll
      for(int q2=0;q2<16;q2++) s += sS[h2][q2][t];
    int y = i1*4 + (t>>2), x = j1*4 + (t&3);
    g_lm[b*4096 + y*64 + x] = s*(1.f/64.f);
  }
}

// ---------------- depthwise lepe conv + concat add ---------------------------
__global__ void lepe_k(const float* __restrict__ lcb){
  int blk = blockIdx.x, c = threadIdx.x;
  int b = blk>>12, pos = blk&4095, y = pos>>6, x = pos&63;
  float acc = lcb[c];
  #pragma unroll
  for(int dy=-1;dy<=1;dy++){
    int yy = y+dy; if((unsigned)yy >= 64u) continue;
    #pragma unroll
    for(int dx=-1;dx<=1;dx++){
      int xx = x+dx; if((unsigned)xx >= 64u) continue;
      int tap = (dy+1)*3 + (dx+1);
      acc = fmaf(g_proj1[((size_t)(b*4096 + yy*64+xx))*768 + 512 + c],
                 g_lwT[tap*256+c], acc);
    }
  }
  size_t o = (size_t)blk*256 + c;
  g_pre[o] = g_cat[o] + acc;
}

// ---------------- mask assembly ----------------------------------------------
__global__ void mask_k(float* __restrict__ out){
  int idx = blockIdx.x*256 + threadIdx.x;      // 0..16383
  int b = idx>>12, pos = idx&4095, y = pos>>6, x = pos&63;
  float v = g_lm[idx] + g_gsum[b*1024 + (y>>1)*32 + (x>>1)] * (1.f/16384.f);
  out[4194304 + idx] = v;                       // mask1 [b, y*64+x]
  out[4210688 + b*4096 + x*64 + y] = v;         // mask2 [b, x*64+y]
}

// ---------------- launch -----------------------------------------------------
extern "C" void kernel_launch(void* const* d_in, const int* in_sizes, int n_in,
                              void* d_out, int out_size)
{
  const float* x    = (const float*)d_in[0];
  const float* q1w  = (const float*)d_in[1];
  const float* q1b  = (const float*)d_in[2];
  const float* kv1w = (const float*)d_in[3];
  const float* kv1b = (const float*)d_in[4];
  const float* q2w  = (const float*)d_in[5];
  const float* q2b  = (const float*)d_in[6];
  const float* kv2w = (const float*)d_in[7];
  const float* kv2b = (const float*)d_in[8];
  const float* lpw  = (const float*)d_in[9];
  const float* lpb  = (const float*)d_in[10];
  const float* lcw  = (const float*)d_in[11];
  const float* lcb  = (const float*)d_in[12];
  const float* srw  = (const float*)d_in[13];
  const float* srb  = (const float*)d_in[14];
  const float* nw   = (const float*)d_in[15];
  const float* nb   = (const float*)d_in[16];
  const float* pw   = (const float*)d_in[17];
  const float* pb   = (const float*)d_in[18];
  float* out = (float*)d_out;

  const int ATTN1_SMEM = (32*1032 + 32*33 + 128*33) * 4;  // 153216 B
  cudaFuncSetAttribute(attn1_k, cudaFuncAttributeMaxDynamicSharedMemorySize, ATTN1_SMEM);

  prep_k<<<256,256>>>(q1w,q2w,kv2w,lpw,q1b,q2b,kv2b,lpb,srw,lcw);
  gemm_k<0><<<dim3(12,256),256>>>(x, nullptr, nullptr, nullptr);     // proj1
  gemm_k<1><<<dim3(4,64),  256>>>(x, nullptr, srb,     nullptr);     // xs_pre
  ln_gelu_k<<<4096,256>>>(nw, nb);
  gemm_k<2><<<dim3(4,64),  256>>>(nullptr, kv1w, kv1b, nullptr);     // kv1
  attn1_k<<<dim3(128,4,4), 256, ATTN1_SMEM>>>();
  gred_k<<<4,1024>>>();
  attn2_k<<<dim3(256,4),256>>>();
  lepe_k<<<16384,256>>>(lcb);
  gemm_k<3><<<dim3(4,256), 256>>>(nullptr, pw, pb, out);             // proj -> out
  mask_k<<<64,256>>>(out);
}